// round 1
// baseline (speedup 1.0000x reference)
#include <cuda_runtime.h>
#include <cuda_bf16.h>

// Problem constants (fixed by dataset)
#define B_DIM 64
#define L_DIM 512
#define ROWS_PER_BLOCK 8      // 8 warps, 1 row each
#define RB_COUNT (L_DIM / ROWS_PER_BLOCK)   // 64 row-blocks per sample

// Per-block partial sums: [B][RB_COUNT][3]  (S1, S2, S3)
__device__ float g_partials[B_DIM * RB_COUNT * 3];

// softplus core: log1p(exp(-|x|)) via fast MUFU ops (EX2 + LG2)
__device__ __forceinline__ float sp_core(float x) {
    return __logf(1.0f + __expf(-fabsf(x)));
}

__global__ __launch_bounds__(256) void partial_kernel(
    const float* __restrict__ inputs,
    const float* __restrict__ targets,
    const int*   __restrict__ seq_lens)
{
    const int rb   = blockIdx.x;          // row-block within sample
    const int b    = blockIdx.y;          // sample
    const int w    = threadIdx.x >> 5;    // warp id = row within row-block
    const int lane = threadIdx.x & 31;

    const int sl  = seq_lens[b];
    const int row = rb * ROWS_PER_BLOCK + w;

    float s1 = 0.0f, s2 = 0.0f, s3 = 0.0f;

    if (row < sl) {
        const size_t base = ((size_t)b * L_DIM + row) * L_DIM;
        const float4* __restrict__ ip = (const float4*)(inputs  + base);
        const float4* __restrict__ tp = (const float4*)(targets + base);

        #pragma unroll
        for (int k = 0; k < L_DIM / 128; k++) {
            const int c = k * 128 + lane * 4;
            if (c < sl) {
                const float4 x4 = ip[c >> 2];
                const float4 t4 = tp[c >> 2];
                const float xs[4] = {x4.x, x4.y, x4.z, x4.w};
                const float ts[4] = {t4.x, t4.y, t4.z, t4.w};
                #pragma unroll
                for (int j = 0; j < 4; j++) {
                    if (c + j < sl) {
                        const float x = xs[j];
                        const float t = ts[j];
                        const float core = sp_core(x);
                        const float sp_neg = core + fmaxf(-x, 0.0f); // softplus(-x)
                        const float sp_pos = core + fmaxf( x, 0.0f); // softplus(x)
                        s1 += t;
                        s2 = fmaf(t, sp_neg, s2);
                        s3 = fmaf(1.0f - t, sp_pos, s3);
                    }
                }
            }
        }
    }

    // warp reduce
    #pragma unroll
    for (int o = 16; o > 0; o >>= 1) {
        s1 += __shfl_xor_sync(0xFFFFFFFFu, s1, o);
        s2 += __shfl_xor_sync(0xFFFFFFFFu, s2, o);
        s3 += __shfl_xor_sync(0xFFFFFFFFu, s3, o);
    }

    __shared__ float red[3][ROWS_PER_BLOCK];
    if (lane == 0) { red[0][w] = s1; red[1][w] = s2; red[2][w] = s3; }
    __syncthreads();

    if (threadIdx.x == 0) {
        float a0 = 0.0f, a1 = 0.0f, a2 = 0.0f;
        #pragma unroll
        for (int i = 0; i < ROWS_PER_BLOCK; i++) {
            a0 += red[0][i]; a1 += red[1][i]; a2 += red[2][i];
        }
        const int idx = (b * RB_COUNT + rb) * 3;
        g_partials[idx + 0] = a0;
        g_partials[idx + 1] = a1;
        g_partials[idx + 2] = a2;
    }
}

__global__ __launch_bounds__(64) void finalize_kernel(
    const int* __restrict__ seq_lens,
    float* __restrict__ out)
{
    const int b = threadIdx.x;   // one thread per sample (B_DIM == 64)

    float s1 = 0.0f, s2 = 0.0f, s3 = 0.0f;
    #pragma unroll 8
    for (int rb = 0; rb < RB_COUNT; rb++) {
        const int idx = (b * RB_COUNT + rb) * 3;
        s1 += g_partials[idx + 0];
        s2 += g_partials[idx + 1];
        s3 += g_partials[idx + 2];
    }

    const float sl_f  = (float)seq_lens[b];
    const float total = sl_f * sl_f;
    const float tmax  = fmaxf(total, 1.0f);
    const float density = (total > 0.0f) ? (s1 / tmax) : 0.0f;
    float w = 0.01f / (density + 1e-6f);
    w = fminf(fmaxf(w, 1.0f), 50.0f);

    const float per_sample = (w * s2 + s3) / tmax;

    // reduce mean over 64 samples (2 warps)
    __shared__ float sh[64];
    sh[b] = per_sample;
    __syncthreads();
    if (b < 32) {
        float v = sh[b] + sh[b + 32];
        #pragma unroll
        for (int o = 16; o > 0; o >>= 1)
            v += __shfl_xor_sync(0xFFFFFFFFu, v, o);
        if (b == 0) out[0] = v / (float)B_DIM;
    }
}

extern "C" void kernel_launch(void* const* d_in, const int* in_sizes, int n_in,
                              void* d_out, int out_size)
{
    const float* inputs   = (const float*)d_in[0];
    const float* targets  = (const float*)d_in[1];
    const int*   seq_lens = (const int*)d_in[2];
    float*       out      = (float*)d_out;

    dim3 grid(RB_COUNT, B_DIM);
    partial_kernel<<<grid, 256>>>(inputs, targets, seq_lens);
    finalize_kernel<<<1, 64>>>(seq_lens, out);
}

// round 6
// speedup vs baseline: 1.3582x; 1.3582x over previous
#include <cuda_runtime.h>
#include <cuda_bf16.h>

// Problem constants (fixed by dataset)
#define B_DIM 64
#define L_DIM 512
#define ROWS_PER_BLOCK 8      // 8 warps, 1 row each
#define RB_COUNT (L_DIM / ROWS_PER_BLOCK)   // 64 row-blocks per sample

// Per-block partial sums: [B][RB_COUNT][3]  (S1, S2, S3)
__device__ float g_partials[B_DIM * RB_COUNT * 3];

// softplus core: log1p(exp(-|x|)) via fast MUFU ops (EX2 + LG2)
__device__ __forceinline__ float sp_core(float x) {
    return __logf(1.0f + __expf(-fabsf(x)));
}

__global__ __launch_bounds__(256) void partial_kernel(
    const float* __restrict__ inputs,
    const float* __restrict__ targets,
    const int*   __restrict__ seq_lens)
{
    const int rb   = blockIdx.x;          // row-block within sample
    const int b    = blockIdx.y;          // sample
    const int w    = threadIdx.x >> 5;    // warp id = row within row-block
    const int lane = threadIdx.x & 31;

    const int sl  = seq_lens[b];
    const int row = rb * ROWS_PER_BLOCK + w;

    float s1 = 0.0f, s2 = 0.0f, s3 = 0.0f;

    if (row < sl) {
        const size_t base = ((size_t)b * L_DIM + row) * L_DIM;
        const float4* __restrict__ ip = (const float4*)(inputs  + base);
        const float4* __restrict__ tp = (const float4*)(targets + base);

        #pragma unroll
        for (int k = 0; k < L_DIM / 128; k++) {
            const int c = k * 128 + lane * 4;
            if (c < sl) {
                const float4 x4 = ip[c >> 2];
                const float4 t4 = tp[c >> 2];
                const float xs[4] = {x4.x, x4.y, x4.z, x4.w};
                const float ts[4] = {t4.x, t4.y, t4.z, t4.w};
                #pragma unroll
                for (int j = 0; j < 4; j++) {
                    if (c + j < sl) {
                        const float x = xs[j];
                        const float t = ts[j];
                        const float core = sp_core(x);
                        const float sp_neg = core + fmaxf(-x, 0.0f); // softplus(-x)
                        const float sp_pos = core + fmaxf( x, 0.0f); // softplus(x)
                        s1 += t;
                        s2 = fmaf(t, sp_neg, s2);
                        s3 = fmaf(1.0f - t, sp_pos, s3);
                    }
                }
            }
        }
    }

    // warp reduce
    #pragma unroll
    for (int o = 16; o > 0; o >>= 1) {
        s1 += __shfl_xor_sync(0xFFFFFFFFu, s1, o);
        s2 += __shfl_xor_sync(0xFFFFFFFFu, s2, o);
        s3 += __shfl_xor_sync(0xFFFFFFFFu, s3, o);
    }

    __shared__ float red[3][ROWS_PER_BLOCK];
    if (lane == 0) { red[0][w] = s1; red[1][w] = s2; red[2][w] = s3; }
    __syncthreads();

    if (threadIdx.x == 0) {
        float a0 = 0.0f, a1 = 0.0f, a2 = 0.0f;
        #pragma unroll
        for (int i = 0; i < ROWS_PER_BLOCK; i++) {
            a0 += red[0][i]; a1 += red[1][i]; a2 += red[2][i];
        }
        const int idx = (b * RB_COUNT + rb) * 3;
        g_partials[idx + 0] = a0;
        g_partials[idx + 1] = a1;
        g_partials[idx + 2] = a2;
    }
}

// Parallel finalize: 1024 threads = 64 samples x 16 threads.
// Each thread loads 4 partial triples (12 independent loads -> one L2 round trip),
// 16-lane subgroup shfl-reduce, then per-sample loss + mean over samples.
__global__ __launch_bounds__(1024) void finalize_kernel(
    const int* __restrict__ seq_lens,
    float* __restrict__ out)
{
    const int tid = threadIdx.x;
    const int b   = tid >> 4;     // 0..63  sample
    const int sub = tid & 15;     // 0..15  lane within sample group

    float s1 = 0.0f, s2 = 0.0f, s3 = 0.0f;
    #pragma unroll
    for (int i = 0; i < RB_COUNT / 16; i++) {
        const int rb  = sub + i * 16;
        const int idx = (b * RB_COUNT + rb) * 3;
        s1 += g_partials[idx + 0];
        s2 += g_partials[idx + 1];
        s3 += g_partials[idx + 2];
    }

    // reduce within the 16-lane subgroup (stays inside one warp half)
    #pragma unroll
    for (int o = 8; o > 0; o >>= 1) {
        s1 += __shfl_xor_sync(0xFFFFFFFFu, s1, o);
        s2 += __shfl_xor_sync(0xFFFFFFFFu, s2, o);
        s3 += __shfl_xor_sync(0xFFFFFFFFu, s3, o);
    }

    __shared__ float sh[B_DIM];
    if (sub == 0) {
        const float sl_f  = (float)seq_lens[b];
        const float total = sl_f * sl_f;
        const float tmax  = fmaxf(total, 1.0f);
        const float density = (total > 0.0f) ? (s1 / tmax) : 0.0f;
        float w = 0.01f / (density + 1e-6f);
        w = fminf(fmaxf(w, 1.0f), 50.0f);
        sh[b] = (w * s2 + s3) / tmax;
    }
    __syncthreads();

    if (tid < 32) {
        float v = sh[tid] + sh[tid + 32];
        #pragma unroll
        for (int o = 16; o > 0; o >>= 1)
            v += __shfl_xor_sync(0xFFFFFFFFu, v, o);
        if (tid == 0) out[0] = v / (float)B_DIM;
    }
}

extern "C" void kernel_launch(void* const* d_in, const int* in_sizes, int n_in,
                              void* d_out, int out_size)
{
    const float* inputs   = (const float*)d_in[0];
    const float* targets  = (const float*)d_in[1];
    const int*   seq_lens = (const int*)d_in[2];
    float*       out      = (float*)d_out;

    dim3 grid(RB_COUNT, B_DIM);
    partial_kernel<<<grid, 256>>>(inputs, targets, seq_lens);
    finalize_kernel<<<1, 1024>>>(seq_lens, out);
}